// round 7
// baseline (speedup 1.0000x reference)
#include <cuda_runtime.h>
#include <cstdint>

#define CIN  256
#define COUT 128
#define HIN  60
#define WIN  80
#define HOUT 120
#define WOUT 160
#define TR   4
#define TC   16
#define NPIX 64          // TR*TC
#define NY   5           // staged input rows per tile
#define NX   12          // staged input cols per tile
#define SPAD 257         // channel pitch for staged input (pad for banks)

// smem layout (floats):
//   [0 .. 15420)          s_in  [NY*NX][SPAD]      (phase 1 only)
//   [15420 .. 18492)      svt   [12][256]          (phase 1 only)
//   [0 .. 16384) uint32   sdwB  [32][64][8]        (after sync, aliases s_in)
#define SMEM_FLOATS (NY*NX*SPAD + 12*256)
#define SMEM_BYTES  (SMEM_FLOATS * 4)

// Pre-repacked, tf32-converted pointwise weights in exact A-fragment register
// order: wA[wid(8)][ks(32)][lane(32)] = {a0,a1,a2,a3} as uint4.
__device__ uint4 wA_buf[8 * 32 * 32];

__device__ __forceinline__ uint32_t f2tf32(float x) {
    uint32_t r;
    asm("cvt.rna.tf32.f32 %0, %1;" : "=r"(r) : "f"(x));
    return r;
}

__global__ void repack_w_kernel(const float* __restrict__ wpw) {
    int t = blockIdx.x * 256 + threadIdx.x;      // 0..8191
    if (t >= 8 * 32 * 32) return;
    int lane = t & 31;
    int ks   = (t >> 5) & 31;
    int wid  = t >> 10;
    int gid = lane >> 2, tig = lane & 3;
    int o0 = wid * 16 + gid;
    int c0 = ks * 8 + tig;
    uint4 v;
    v.x = f2tf32(wpw[(size_t)o0 * CIN + c0]);          // a0: (o0,   c0)
    v.y = f2tf32(wpw[(size_t)(o0 + 8) * CIN + c0]);    // a1: (o0+8, c0)
    v.z = f2tf32(wpw[(size_t)o0 * CIN + c0 + 4]);      // a2: (o0,   c0+4)
    v.w = f2tf32(wpw[(size_t)(o0 + 8) * CIN + c0 + 4]);// a3: (o0+8, c0+4)
    wA_buf[t] = v;
}

__global__ __launch_bounds__(256, 2)
void fused_upconv_kernel(const float* __restrict__ x,
                         const float* __restrict__ wdw,
                         float* __restrict__ out)
{
    extern __shared__ float smem[];
    float*    s_in = smem;                       // [NY*NX][SPAD]
    float*    svt  = smem + NY * NX * SPAD;      // [12][256]
    uint32_t* sdwB = (uint32_t*)smem;            // [32][64][8], reused after sync

    const int tileX = blockIdx.x;   // 0..9
    const int tileY = blockIdx.y;   // 0..29
    const int b     = blockIdx.z;   // 0..7
    const int tid   = threadIdx.x;

    const int r0  = tileY * TR;     // first output row
    const int xo0 = tileX * TC;     // first output col (== first RES col)

    const float CY = 59.0f / 121.0f;   // (HIN-1)/(RES_H-1), matches ref f32
    const float CX = 79.0f / 161.0f;   // (WIN-1)/(RES_W-1)

    const int y_lo = (int)((float)r0 * CY);
    const int ixb  = (int)((float)xo0 * CX);

    // ---- Stage input patch: all 256 channels, NY rows x NX cols, coalesced ----
    {
        const size_t bbase = (size_t)b * CIN * (HIN * WIN);
        for (int idx = tid; idx < CIN * NY * NX; idx += 256) {
            int c   = idx / (NY * NX);
            int rem = idx - c * (NY * NX);
            int yy  = rem / NX;
            int ix  = rem - yy * NX;
            int gy  = min(y_lo + yy, HIN - 1);
            int gx  = min(ixb + ix, WIN - 1);
            s_in[(yy * NX + ix) * SPAD + c] =
                x[bbase + (size_t)c * (HIN * WIN) + gy * WIN + gx];
        }
    }
    __syncthreads();

    // ---- Phase 1: bilinear upsample + 3x3 depthwise, channel c = tid ----
    float acc[TR][TC];
    {
        const int c = tid;
        float wd[9];
        #pragma unroll
        for (int i = 0; i < 9; i++) wd[i] = __ldg(&wdw[c * 9 + i]);

        #pragma unroll
        for (int r = 0; r < TR; r++)
            #pragma unroll
            for (int q = 0; q < TC; q++) acc[r][q] = 0.0f;

        #pragma unroll
        for (int rho = 0; rho < 6; rho++) {
            const int R = r0 + rho;                 // RES row
            float hy = (float)R * CY;
            int   y0 = (int)hy;
            float fy = hy - (float)y0;
            int   y1 = min(y0 + 1, HIN - 1);
            float ofy = 1.0f - fy;
            const int ry0 = y0 - y_lo;
            const int ry1 = y1 - y_lo;

            // vertical lerp into per-thread smem column
            #pragma unroll
            for (int i = 0; i < 12; i++) {
                float a0 = s_in[(ry0 * NX + i) * SPAD + c];
                float a1 = s_in[(ry1 * NX + i) * SPAD + c];
                svt[i * 256 + c] = a0 * ofy + a1 * fy;
            }

            // horizontal lerp + conv accumulation
            #pragma unroll
            for (int xi = 0; xi < 18; xi++) {
                float wxv = (float)(xo0 + xi) * CX;
                int   x0i = (int)wxv;
                float fx  = wxv - (float)x0i;
                int   x1i = min(x0i + 1, WIN - 1);
                float v0 = svt[(x0i - ixb) * 256 + c];
                float v1 = svt[(x1i - ixb) * 256 + c];
                float u  = v0 * (1.0f - fx) + v1 * fx;
                #pragma unroll
                for (int dy = 0; dy < 3; dy++) {
                    int r = rho - dy;
                    if (r < 0 || r >= TR) continue;
                    #pragma unroll
                    for (int dx = 0; dx < 3; dx++) {
                        int q = xi - dx;
                        if (q < 0 || q >= TC) continue;
                        acc[r][q] += wd[dy * 3 + dx] * u;
                    }
                }
            }
        }
    }
    __syncthreads();   // s_in / svt dead; safe to alias with sdwB

    // ---- Store dw tile, tf32-converted, in B-fragment-friendly interleave ----
    {
        const int c     = tid;
        const int ks    = c >> 3;
        const int inner = ((c & 3) << 1) | ((c >> 2) & 1);  // (tig,tig+4) adjacent
        #pragma unroll
        for (int r = 0; r < TR; r++)
            #pragma unroll
            for (int q = 0; q < TC; q++) {
                int p = r * TC + q;
                sdwB[(ks * 64 + p) * 8 + inner] = f2tf32(acc[r][q]);
            }
    }
    __syncthreads();

    // ---- Phase 2: tf32 mma GEMM  out[o][p] = sum_c W[o][c] * dw[c][p] ----
    {
        const int wid  = tid >> 5;
        const int lane = tid & 31;
        const int gid  = lane >> 2;
        const int tig  = lane & 3;
        const int oA   = wid * 16;

        float d[8][4];
        #pragma unroll
        for (int nt = 0; nt < 8; nt++)
            #pragma unroll
            for (int i = 0; i < 4; i++) d[nt][i] = 0.0f;

        const uint4* wAp = wA_buf + (size_t)wid * 32 * 32 + lane;

        #pragma unroll 4
        for (int ks = 0; ks < 32; ks++) {
            uint4 av = __ldg(&wAp[ks * 32]);   // a0..a3, coalesced, L1-hot
            #pragma unroll
            for (int nt = 0; nt < 8; nt++) {
                uint2 bb = *(const uint2*)&sdwB[(ks * 64 + nt * 8 + gid) * 8 + 2 * tig];
                asm volatile(
                    "mma.sync.aligned.m16n8k8.row.col.f32.tf32.tf32.f32 "
                    "{%0,%1,%2,%3}, {%4,%5,%6,%7}, {%8,%9}, {%0,%1,%2,%3};"
                    : "+f"(d[nt][0]), "+f"(d[nt][1]), "+f"(d[nt][2]), "+f"(d[nt][3])
                    : "r"(av.x), "r"(av.y), "r"(av.z), "r"(av.w),
                      "r"(bb.x), "r"(bb.y));
            }
        }

        // writeback: d0,d1 -> row (oA+gid), d2,d3 -> row (oA+gid+8)
        #pragma unroll
        for (int nt = 0; nt < 8; nt++) {
            int p = nt * 8 + 2 * tig;
            int h = r0 + (p >> 4);
            int w = xo0 + (p & 15);
            size_t base0 = (((size_t)b * COUT + (oA + gid)) * HOUT + h) * (size_t)WOUT + w;
            size_t base1 = (((size_t)b * COUT + (oA + gid + 8)) * HOUT + h) * (size_t)WOUT + w;
            *(float2*)&out[base0] = make_float2(d[nt][0], d[nt][1]);
            *(float2*)&out[base1] = make_float2(d[nt][2], d[nt][3]);
        }
    }
}

extern "C" void kernel_launch(void* const* d_in, const int* in_sizes, int n_in,
                              void* d_out, int out_size)
{
    const float* x   = (const float*)d_in[0];   // [8,256,60,80]
    const float* wdw = (const float*)d_in[1];   // [256,1,3,3]
    const float* wpw = (const float*)d_in[2];   // [128,256]
    float*       out = (float*)d_out;           // [8,128,120,160]
    (void)in_sizes; (void)n_in; (void)out_size;

    cudaFuncSetAttribute(fused_upconv_kernel,
                         cudaFuncAttributeMaxDynamicSharedMemorySize, SMEM_BYTES);

    repack_w_kernel<<<32, 256>>>(wpw);

    dim3 grid(WOUT / TC, HOUT / TR, 8);   // (10, 30, 8)
    fused_upconv_kernel<<<grid, 256, SMEM_BYTES>>>(x, wdw, out);
}

// round 11
// speedup vs baseline: 1.2170x; 1.2170x over previous
#include <cuda_runtime.h>
#include <cstdint>

#define CIN  256
#define COUT 128
#define HIN  60
#define WIN  80
#define HOUT 120
#define WOUT 160
#define TR   4
#define TC   16
#define NY   5           // staged input rows per tile
#define NX   12          // staged input cols per tile
#define SPAD 257         // channel pitch for staged input (bank-friendly)

// B tile: pixel-major, pitch 260 floats (260 % 32 == 4 -> conflict-free
// scalar stores (addr=c+const) AND conflict-free fragment loads (4*gid+tig)).
#define BPITCH 260
#define SMEM_FLOATS (64 * BPITCH)          // 16640 > 60*257=15420 (s_in aliases)
#define SMEM_BYTES  (SMEM_FLOATS * 4)      // 66560 B

// exact fp32 constants (double ratio rounded once to f32, same as reference)
constexpr float CXc = (float)(79.0 / 161.0);
constexpr float CYc = (float)(59.0 / 121.0);

// ---- compile-time horizontal lerp pattern per tileX (10 variants) ----
struct XPat { int d0[18]; int d1[18]; float fx[18]; };

__host__ __device__ constexpr XPat make_xpat(int tx) {
    XPat p{};
    int xo0 = tx * 16;
    int ixb = (int)((float)xo0 * CXc);
    for (int xi = 0; xi < 18; xi++) {
        float wx = (float)(xo0 + xi) * CXc;   // identical fp32 op as runtime/ref
        int x0 = (int)wx;
        int x1 = x0 + 1; if (x1 > WIN - 1) x1 = WIN - 1;
        p.d0[xi] = x0 - ixb;
        p.d1[xi] = x1 - ixb;
        p.fx[xi] = wx - (float)x0;
    }
    return p;
}

template <int TX>
__device__ __forceinline__ void horiz(const float vt[12], float u[18]) {
    constexpr XPat P = make_xpat(TX);
#pragma unroll
    for (int xi = 0; xi < 18; xi++) {
        // same formula/order as the passing kernel: v0*(1-fx) + v1*fx
        u[xi] = vt[P.d0[xi]] * (1.0f - P.fx[xi]) + vt[P.d1[xi]] * P.fx[xi];
    }
}

__device__ __forceinline__ void horiz_dispatch(int tx, const float vt[12], float u[18]) {
    switch (tx) {
        case 0: horiz<0>(vt, u); break;
        case 1: horiz<1>(vt, u); break;
        case 2: horiz<2>(vt, u); break;
        case 3: horiz<3>(vt, u); break;
        case 4: horiz<4>(vt, u); break;
        case 5: horiz<5>(vt, u); break;
        case 6: horiz<6>(vt, u); break;
        case 7: horiz<7>(vt, u); break;
        case 8: horiz<8>(vt, u); break;
        default: horiz<9>(vt, u); break;
    }
}

// Pre-repacked, tf32-converted pointwise weights in exact A-fragment register
// order: wA[mtile(8)][ks(32)][lane(32)] = {a0,a1,a2,a3} as uint4.
__device__ uint4 wA_buf[8 * 32 * 32];

__device__ __forceinline__ uint32_t f2tf32(float x) {
    uint32_t r;
    asm("cvt.rna.tf32.f32 %0, %1;" : "=r"(r) : "f"(x));
    return r;
}

__device__ __forceinline__ void mma_tf32(float d[4], uint4 a, uint32_t b0, uint32_t b1) {
    asm volatile(
        "mma.sync.aligned.m16n8k8.row.col.f32.tf32.tf32.f32 "
        "{%0,%1,%2,%3}, {%4,%5,%6,%7}, {%8,%9}, {%0,%1,%2,%3};"
        : "+f"(d[0]), "+f"(d[1]), "+f"(d[2]), "+f"(d[3])
        : "r"(a.x), "r"(a.y), "r"(a.z), "r"(a.w), "r"(b0), "r"(b1));
}

__global__ void repack_w_kernel(const float* __restrict__ wpw) {
    int t = blockIdx.x * 256 + threadIdx.x;      // 0..8191
    if (t >= 8 * 32 * 32) return;
    int lane = t & 31;
    int ks   = (t >> 5) & 31;
    int mt   = t >> 10;
    int gid = lane >> 2, tig = lane & 3;
    int o0 = mt * 16 + gid;
    int c0 = ks * 8 + tig;
    uint4 v;
    v.x = f2tf32(wpw[(size_t)o0 * CIN + c0]);           // a0: (o0,   c0)
    v.y = f2tf32(wpw[(size_t)(o0 + 8) * CIN + c0]);     // a1: (o0+8, c0)
    v.z = f2tf32(wpw[(size_t)o0 * CIN + c0 + 4]);       // a2: (o0,   c0+4)
    v.w = f2tf32(wpw[(size_t)(o0 + 8) * CIN + c0 + 4]); // a3: (o0+8, c0+4)
    wA_buf[t] = v;
}

__global__ __launch_bounds__(256, 2)
void fused_upconv_kernel(const float* __restrict__ x,
                         const float* __restrict__ wdw,
                         float* __restrict__ out)
{
    extern __shared__ float smem[];
    float*    s_in = smem;                   // [NY*NX][SPAD]   (phase 1)
    uint32_t* sdwB = (uint32_t*)smem;        // [64 px][BPITCH] (phase 2, aliases)

    const int tileX = blockIdx.x;   // 0..9
    const int tileY = blockIdx.y;   // 0..29
    const int b     = blockIdx.z;   // 0..7
    const int tid   = threadIdx.x;

    const int r0  = tileY * TR;
    const int xo0 = tileX * TC;

    const int y_lo = (int)((float)r0 * CYc);
    const int ixb  = (int)((float)xo0 * CXc);

    // ---- Stage input patch: 256 channels x NY x NX, coalesced ----
    {
        const size_t bbase = (size_t)b * CIN * (HIN * WIN);
        for (int idx = tid; idx < CIN * NY * NX; idx += 256) {
            int c   = idx / (NY * NX);
            int rem = idx - c * (NY * NX);
            int yy  = rem / NX;
            int ix  = rem - yy * NX;
            int gy  = min(y_lo + yy, HIN - 1);
            int gx  = min(ixb + ix, WIN - 1);
            s_in[(yy * NX + ix) * SPAD + c] =
                x[bbase + (size_t)c * (HIN * WIN) + gy * WIN + gx];
        }
    }
    __syncthreads();

    // ---- Phase 1: bilinear + 3x3 depthwise, channel c = tid, all in regs ----
    float acc[TR][TC];
    {
        const int c = tid;
        float wd[9];
        #pragma unroll
        for (int i = 0; i < 9; i++) wd[i] = __ldg(&wdw[c * 9 + i]);

        #pragma unroll
        for (int r = 0; r < TR; r++)
            #pragma unroll
            for (int q = 0; q < TC; q++) acc[r][q] = 0.0f;

        #pragma unroll
        for (int rho = 0; rho < 6; rho++) {
            const int R = r0 + rho;
            float hy = (float)R * CYc;
            int   y0 = (int)hy;
            float fy = hy - (float)y0;
            int   y1 = min(y0 + 1, HIN - 1);
            float ofy = 1.0f - fy;
            const float* p0 = s_in + (y0 - y_lo) * (NX * SPAD) + c;
            const float* p1 = s_in + (y1 - y_lo) * (NX * SPAD) + c;

            float vt[12];
            #pragma unroll
            for (int i = 0; i < 12; i++)
                vt[i] = p0[i * SPAD] * ofy + p1[i * SPAD] * fy;

            float u[18];
            horiz_dispatch(tileX, vt, u);

            #pragma unroll
            for (int dy = 0; dy < 3; dy++) {
                int r = rho - dy;
                if (r < 0 || r >= TR) continue;   // compile-time folded
                #pragma unroll
                for (int dx = 0; dx < 3; dx++) {
                    float wv = wd[dy * 3 + dx];
                    #pragma unroll
                    for (int q = 0; q < TC; q++)
                        acc[r][q] += wv * u[q + dx];
                }
            }
        }
    }
    __syncthreads();   // s_in reads done -> safe to alias with sdwB

    // ---- Store dw tile, tf32, pixel-major [p][c] (conflict-free stores) ----
    {
        const int c = tid;
        #pragma unroll
        for (int p = 0; p < 64; p++)
            sdwB[p * BPITCH + c] = f2tf32(acc[p >> 4][p & 15]);
    }
    __syncthreads();

    // ---- Phase 2: tf32 mma GEMM, m32n32 per warp ----
    {
        const int wid  = tid >> 5;
        const int lane = tid & 31;
        const int gid  = lane >> 2;
        const int tig  = lane & 3;
        const int mg   = wid >> 1;    // 0..3 -> out channels 32*mg..
        const int ng   = wid & 1;     // 0..1 -> pixels 32*ng..

        float d[2][4][4];
        #pragma unroll
        for (int mt = 0; mt < 2; mt++)
            #pragma unroll
            for (int nt = 0; nt < 4; nt++)
                #pragma unroll
                for (int i = 0; i < 4; i++) d[mt][nt][i] = 0.0f;

        const uint4* wAp0 = wA_buf + (size_t)(2 * mg) * 32 * 32 + lane;
        const uint4* wAp1 = wAp0 + 32 * 32;

        int bbase[4];
        #pragma unroll
        for (int nt = 0; nt < 4; nt++)
            bbase[nt] = (ng * 32 + nt * 8 + gid) * BPITCH;

        #pragma unroll 4
        for (int ks = 0; ks < 32; ks++) {
            uint4 a0 = __ldg(wAp0 + ks * 32);
            uint4 a1 = __ldg(wAp1 + ks * 32);
            int ko = ks * 8 + tig;
            #pragma unroll
            for (int nt = 0; nt < 4; nt++) {
                uint32_t b0 = sdwB[bbase[nt] + ko];       // k = tig
                uint32_t b1 = sdwB[bbase[nt] + ko + 4];   // k = tig+4
                mma_tf32(d[0][nt], a0, b0, b1);
                mma_tf32(d[1][nt], a1, b0, b1);
            }
        }

        // writeback: c0,c1 -> row (o), c2,c3 -> row (o+8)
        #pragma unroll
        for (int mt = 0; mt < 2; mt++) {
            int o = mg * 32 + mt * 16 + gid;
            #pragma unroll
            for (int nt = 0; nt < 4; nt++) {
                int p = ng * 32 + nt * 8 + 2 * tig;
                int h = r0 + (p >> 4);
                int w = xo0 + (p & 15);
                size_t base0 = (((size_t)b * COUT + o) * HOUT + h) * (size_t)WOUT + w;
                size_t base1 = (((size_t)b * COUT + o + 8) * HOUT + h) * (size_t)WOUT + w;
                *(float2*)&out[base0] = make_float2(d[mt][nt][0], d[mt][nt][1]);
                *(float2*)&out[base1] = make_float2(d[mt][nt][2], d[mt][nt][3]);
            }
        }
    }
}

extern "C" void kernel_launch(void* const* d_in, const int* in_sizes, int n_in,
                              void* d_out, int out_size)
{
    const float* x   = (const float*)d_in[0];   // [8,256,60,80]
    const float* wdw = (const float*)d_in[1];   // [256,1,3,3]
    const float* wpw = (const float*)d_in[2];   // [128,256]
    float*       out = (float*)d_out;           // [8,128,120,160]
    (void)in_sizes; (void)n_in; (void)out_size;

    cudaFuncSetAttribute(fused_upconv_kernel,
                         cudaFuncAttributeMaxDynamicSharedMemorySize, SMEM_BYTES);

    repack_w_kernel<<<32, 256>>>(wpw);

    dim3 grid(WOUT / TC, HOUT / TR, 8);   // (10, 30, 8)
    fused_upconv_kernel<<<grid, 256, SMEM_BYTES>>>(x, wdw, out);
}

// round 13
// speedup vs baseline: 1.7015x; 1.3981x over previous
#include <cuda_runtime.h>
#include <cstdint>

#define CIN  256
#define COUT 128
#define HIN  60
#define WIN  80
#define HOUT 120
#define WOUT 160
#define TR   4
#define TC   16
#define NY   5           // staged input rows per tile
#define NX   12          // staged input cols per tile
#define SPAD 257         // channel pitch for staged input (bank-friendly)

// B tile: pixel-major, word = p*BP2 + ks*8 + inner, inner interleaves
// (tig, tig+4) into adjacent words -> one LDS.64 per fragment.
// BP2=264: stores are a lane->bank bijection (conflict-free); LDS.64 loads
// hit every bank exactly twice = the 2-phase floor (conflict-free).
#define BP2 264
#define SMEM_WORDS (64 * BP2)              // 16896 > 60*257=15420 (s_in aliases)
#define SMEM_BYTES (SMEM_WORDS * 4)        // 67584 B -> 2 CTAs/SM

// exact fp32 constants (double ratio rounded once to f32, same as reference)
constexpr float CXc = (float)(79.0 / 161.0);
constexpr float CYc = (float)(59.0 / 121.0);

// ---- compile-time horizontal lerp pattern per tileX (10 variants) ----
struct XPat { int d0[18]; int d1[18]; float fx[18]; };

__host__ __device__ constexpr XPat make_xpat(int tx) {
    XPat p{};
    int xo0 = tx * 16;
    int ixb = (int)((float)xo0 * CXc);
    for (int xi = 0; xi < 18; xi++) {
        float wx = (float)(xo0 + xi) * CXc;   // identical fp32 op as reference
        int x0 = (int)wx;
        int x1 = x0 + 1; if (x1 > WIN - 1) x1 = WIN - 1;
        p.d0[xi] = x0 - ixb;
        p.d1[xi] = x1 - ixb;
        p.fx[xi] = wx - (float)x0;
    }
    return p;
}

template <int TX>
__device__ __forceinline__ void horiz(const float vt[12], float u[18]) {
    constexpr XPat P = make_xpat(TX);
#pragma unroll
    for (int xi = 0; xi < 18; xi++) {
        u[xi] = vt[P.d0[xi]] * (1.0f - P.fx[xi]) + vt[P.d1[xi]] * P.fx[xi];
    }
}

__device__ __forceinline__ void horiz_dispatch(int tx, const float vt[12], float u[18]) {
    switch (tx) {
        case 0: horiz<0>(vt, u); break;
        case 1: horiz<1>(vt, u); break;
        case 2: horiz<2>(vt, u); break;
        case 3: horiz<3>(vt, u); break;
        case 4: horiz<4>(vt, u); break;
        case 5: horiz<5>(vt, u); break;
        case 6: horiz<6>(vt, u); break;
        case 7: horiz<7>(vt, u); break;
        case 8: horiz<8>(vt, u); break;
        default: horiz<9>(vt, u); break;
    }
}

// Pre-repacked, tf32-converted pointwise weights in exact A-fragment register
// order: wA[mtile(8)][ks(32)][lane(32)] = {a0,a1,a2,a3} as uint4.
__device__ uint4 wA_buf[8 * 32 * 32];

__device__ __forceinline__ uint32_t f2tf32(float x) {
    uint32_t r;
    asm("cvt.rna.tf32.f32 %0, %1;" : "=r"(r) : "f"(x));
    return r;
}

__device__ __forceinline__ void mma_tf32(float d[4], uint4 a, uint32_t b0, uint32_t b1) {
    asm volatile(
        "mma.sync.aligned.m16n8k8.row.col.f32.tf32.tf32.f32 "
        "{%0,%1,%2,%3}, {%4,%5,%6,%7}, {%8,%9}, {%0,%1,%2,%3};"
        : "+f"(d[0]), "+f"(d[1]), "+f"(d[2]), "+f"(d[3])
        : "r"(a.x), "r"(a.y), "r"(a.z), "r"(a.w), "r"(b0), "r"(b1));
}

__global__ void repack_w_kernel(const float* __restrict__ wpw) {
    int t = blockIdx.x * 256 + threadIdx.x;      // 0..8191
    if (t >= 8 * 32 * 32) return;
    int lane = t & 31;
    int ks   = (t >> 5) & 31;
    int mt   = t >> 10;
    int gid = lane >> 2, tig = lane & 3;
    int o0 = mt * 16 + gid;
    int c0 = ks * 8 + tig;
    uint4 v;
    v.x = f2tf32(wpw[(size_t)o0 * CIN + c0]);           // a0: (o0,   c0)
    v.y = f2tf32(wpw[(size_t)(o0 + 8) * CIN + c0]);     // a1: (o0+8, c0)
    v.z = f2tf32(wpw[(size_t)o0 * CIN + c0 + 4]);       // a2: (o0,   c0+4)
    v.w = f2tf32(wpw[(size_t)(o0 + 8) * CIN + c0 + 4]); // a3: (o0+8, c0+4)
    wA_buf[t] = v;
}

__global__ __launch_bounds__(256, 2)
void fused_upconv_kernel(const float* __restrict__ x,
                         const float* __restrict__ wdw,
                         float* __restrict__ out)
{
    extern __shared__ float smem[];
    float*    s_in = smem;                   // [NY*NX][SPAD]      (phase 1)
    uint32_t* sdwB = (uint32_t*)smem;        // [64 px][BP2] words (phase 2, aliases)

    const int tileX = blockIdx.x;   // 0..9
    const int tileY = blockIdx.y;   // 0..29
    const int b     = blockIdx.z;   // 0..7
    const int tid   = threadIdx.x;

    const int r0  = tileY * TR;
    const int xo0 = tileX * TC;

    const int y_lo = (int)((float)r0 * CYc);
    const int ixb  = (int)((float)xo0 * CXc);

    // ---- Stage input patch: thread = (patch position, channel group).
    //      All index math hoisted; body is pure LDG+STS with const strides. ----
    {
        const int pos  = tid & 63;          // 0..63, 0..59 valid
        const int cgrp = tid >> 6;          // 0..3
        if (pos < NY * NX) {
            const int yy = pos / NX;
            const int ix = pos - yy * NX;
            const int gy = min(y_lo + yy, HIN - 1);
            const int gx = min(ixb + ix, WIN - 1);
            const float* gp = x + (size_t)b * CIN * (HIN * WIN)
                                + (size_t)cgrp * (HIN * WIN) + gy * WIN + gx;
            float* sp = s_in + pos * SPAD + cgrp;
            #pragma unroll 16
            for (int k = 0; k < 64; k++)
                sp[k * 4] = __ldg(gp + (size_t)k * 4 * (HIN * WIN));
        }
    }
    __syncthreads();

    // ---- Phase 1: bilinear + 3x3 depthwise, channel c = tid, all in regs ----
    float acc[TR][TC];
    {
        const int c = tid;
        float wd[9];
        #pragma unroll
        for (int i = 0; i < 9; i++) wd[i] = __ldg(&wdw[c * 9 + i]);

        #pragma unroll
        for (int r = 0; r < TR; r++)
            #pragma unroll
            for (int q = 0; q < TC; q++) acc[r][q] = 0.0f;

        #pragma unroll
        for (int rho = 0; rho < 6; rho++) {
            const int R = r0 + rho;
            float hy = (float)R * CYc;
            int   y0 = (int)hy;
            float fy = hy - (float)y0;
            int   y1 = min(y0 + 1, HIN - 1);
            float ofy = 1.0f - fy;
            const float* p0 = s_in + (y0 - y_lo) * (NX * SPAD) + c;
            const float* p1 = s_in + (y1 - y_lo) * (NX * SPAD) + c;

            float vt[12];
            #pragma unroll
            for (int i = 0; i < 12; i++)
                vt[i] = p0[i * SPAD] * ofy + p1[i * SPAD] * fy;

            float u[18];
            horiz_dispatch(tileX, vt, u);

            #pragma unroll
            for (int dy = 0; dy < 3; dy++) {
                int r = rho - dy;
                if (r < 0 || r >= TR) continue;   // compile-time folded
                #pragma unroll
                for (int dx = 0; dx < 3; dx++) {
                    float wv = wd[dy * 3 + dx];
                    #pragma unroll
                    for (int q = 0; q < TC; q++)
                        acc[r][q] += wv * u[q + dx];
                }
            }
        }
    }
    __syncthreads();   // s_in reads done -> safe to alias with sdwB

    // ---- Store dw tile, tf32: word = p*BP2 + (c>>3)*8 + inner.
    //      Lane->bank map is a bijection -> conflict-free stores. ----
    {
        const int c = tid;
        const int soff = ((c >> 3) << 3) | (((c & 3) << 1) | ((c >> 2) & 1));
        uint32_t* sp = sdwB + soff;
        #pragma unroll
        for (int p = 0; p < 64; p++)
            sp[p * BP2] = f2tf32(acc[p >> 4][p & 15]);
    }
    __syncthreads();

    // ---- Phase 2: tf32 mma GEMM, m32n32 per warp, LDS.64 B fragments ----
    {
        const int wid  = tid >> 5;
        const int lane = tid & 31;
        const int gid  = lane >> 2;
        const int tig  = lane & 3;
        const int mg   = wid >> 1;    // 0..3 -> out channels 32*mg..
        const int ng   = wid & 1;     // 0..1 -> pixels 32*ng..

        float d[2][4][4];
        #pragma unroll
        for (int mt = 0; mt < 2; mt++)
            #pragma unroll
            for (int nt = 0; nt < 4; nt++)
                #pragma unroll
                for (int i = 0; i < 4; i++) d[mt][nt][i] = 0.0f;

        const uint4* wAp0 = wA_buf + (size_t)(2 * mg) * 32 * 32 + lane;
        const uint4* wAp1 = wAp0 + 32 * 32;

        const uint32_t* bp[4];
        #pragma unroll
        for (int nt = 0; nt < 4; nt++)
            bp[nt] = sdwB + (ng * 32 + nt * 8 + gid) * BP2 + 2 * tig;

        #pragma unroll 8
        for (int ks = 0; ks < 32; ks++) {
            uint4 a0 = __ldg(wAp0 + ks * 32);
            uint4 a1 = __ldg(wAp1 + ks * 32);
            #pragma unroll
            for (int nt = 0; nt < 4; nt++) {
                uint2 bb = *(const uint2*)(bp[nt] + ks * 8);  // k=tig, k=tig+4
                mma_tf32(d[0][nt], a0, bb.x, bb.y);
                mma_tf32(d[1][nt], a1, bb.x, bb.y);
            }
        }

        // writeback: c0,c1 -> row (o), c2,c3 -> row (o+8)
        #pragma unroll
        for (int mt = 0; mt < 2; mt++) {
            int o = mg * 32 + mt * 16 + gid;
            #pragma unroll
            for (int nt = 0; nt < 4; nt++) {
                int p = ng * 32 + nt * 8 + 2 * tig;
                int h = r0 + (p >> 4);
                int w = xo0 + (p & 15);
                size_t base0 = (((size_t)b * COUT + o) * HOUT + h) * (size_t)WOUT + w;
                size_t base1 = (((size_t)b * COUT + o + 8) * HOUT + h) * (size_t)WOUT + w;
                *(float2*)&out[base0] = make_float2(d[mt][nt][0], d[mt][nt][1]);
                *(float2*)&out[base1] = make_float2(d[mt][nt][2], d[mt][nt][3]);
            }
        }
    }
}

extern "C" void kernel_launch(void* const* d_in, const int* in_sizes, int n_in,
                              void* d_out, int out_size)
{
    const float* x   = (const float*)d_in[0];   // [8,256,60,80]
    const float* wdw = (const float*)d_in[1];   // [256,1,3,3]
    const float* wpw = (const float*)d_in[2];   // [128,256]
    float*       out = (float*)d_out;           // [8,128,120,160]
    (void)in_sizes; (void)n_in; (void)out_size;

    cudaFuncSetAttribute(fused_upconv_kernel,
                         cudaFuncAttributeMaxDynamicSharedMemorySize, SMEM_BYTES);

    repack_w_kernel<<<32, 256>>>(wpw);

    dim3 grid(WOUT / TC, HOUT / TR, 8);   // (10, 30, 8)
    fused_upconv_kernel<<<grid, 256, SMEM_BYTES>>>(x, wdw, out);
}

// round 14
// speedup vs baseline: 1.7308x; 1.0172x over previous
#include <cuda_runtime.h>
#include <cstdint>

#define CIN  256
#define COUT 128
#define HIN  60
#define WIN  80
#define HOUT 120
#define WOUT 160
#define TR   4
#define TC   16
#define NY   5           // staged input rows per tile
#define NX   12          // staged input cols per tile
#define SPAD 257         // channel pitch for staged input (bank-friendly)

// B tile: pixel-major, word = p*BP2 + ks*8 + inner, inner interleaves
// (tig, tig+4) into adjacent words -> one LDS.64 per fragment.
// BP2=264: stores are a lane->bank bijection (conflict-free); LDS.64 loads
// hit every bank exactly twice = the 2-phase floor (conflict-free).
#define BP2 264
#define SMEM_WORDS (64 * BP2)              // 16896 > 60*257=15420 (s_in aliases)
#define SMEM_BYTES (SMEM_WORDS * 4)        // 67584 B -> 2 CTAs/SM

// exact fp32 constants (double ratio rounded once to f32, same as reference)
constexpr float CXc = (float)(79.0 / 161.0);
constexpr float CYc = (float)(59.0 / 121.0);

// ---- compile-time horizontal lerp pattern per tileX (10 variants) ----
struct XPat { int d0[18]; int d1[18]; float fx[18]; };

__host__ __device__ constexpr XPat make_xpat(int tx) {
    XPat p{};
    int xo0 = tx * 16;
    int ixb = (int)((float)xo0 * CXc);
    for (int xi = 0; xi < 18; xi++) {
        float wx = (float)(xo0 + xi) * CXc;   // identical fp32 op as reference
        int x0 = (int)wx;
        int x1 = x0 + 1; if (x1 > WIN - 1) x1 = WIN - 1;
        p.d0[xi] = x0 - ixb;
        p.d1[xi] = x1 - ixb;
        p.fx[xi] = wx - (float)x0;
    }
    return p;
}

template <int TX>
__device__ __forceinline__ void horiz(const float vt[12], float u[18]) {
    constexpr XPat P = make_xpat(TX);
#pragma unroll
    for (int xi = 0; xi < 18; xi++) {
        u[xi] = vt[P.d0[xi]] * (1.0f - P.fx[xi]) + vt[P.d1[xi]] * P.fx[xi];
    }
}

__device__ __forceinline__ void horiz_dispatch(int tx, const float vt[12], float u[18]) {
    switch (tx) {
        case 0: horiz<0>(vt, u); break;
        case 1: horiz<1>(vt, u); break;
        case 2: horiz<2>(vt, u); break;
        case 3: horiz<3>(vt, u); break;
        case 4: horiz<4>(vt, u); break;
        case 5: horiz<5>(vt, u); break;
        case 6: horiz<6>(vt, u); break;
        case 7: horiz<7>(vt, u); break;
        case 8: horiz<8>(vt, u); break;
        default: horiz<9>(vt, u); break;
    }
}

// Pre-repacked, tf32-converted pointwise weights in exact A-fragment register
// order: wA[mtile(8)][ks(32)][lane(32)] = {a0,a1,a2,a3} as uint4.
__device__ uint4 wA_buf[8 * 32 * 32];

__device__ __forceinline__ uint32_t f2tf32(float x) {
    uint32_t r;
    asm("cvt.rna.tf32.f32 %0, %1;" : "=r"(r) : "f"(x));
    return r;
}

__device__ __forceinline__ void mma_tf32(float d[4], uint4 a, uint32_t b0, uint32_t b1) {
    asm volatile(
        "mma.sync.aligned.m16n8k8.row.col.f32.tf32.tf32.f32 "
        "{%0,%1,%2,%3}, {%4,%5,%6,%7}, {%8,%9}, {%0,%1,%2,%3};"
        : "+f"(d[0]), "+f"(d[1]), "+f"(d[2]), "+f"(d[3])
        : "r"(a.x), "r"(a.y), "r"(a.z), "r"(a.w), "r"(b0), "r"(b1));
}

__global__ void repack_w_kernel(const float* __restrict__ wpw) {
    int t = blockIdx.x * 256 + threadIdx.x;      // 0..8191
    if (t >= 8 * 32 * 32) return;
    int lane = t & 31;
    int ks   = (t >> 5) & 31;
    int mt   = t >> 10;
    int gid = lane >> 2, tig = lane & 3;
    int o0 = mt * 16 + gid;
    int c0 = ks * 8 + tig;
    uint4 v;
    v.x = f2tf32(wpw[(size_t)o0 * CIN + c0]);           // a0: (o0,   c0)
    v.y = f2tf32(wpw[(size_t)(o0 + 8) * CIN + c0]);     // a1: (o0+8, c0)
    v.z = f2tf32(wpw[(size_t)o0 * CIN + c0 + 4]);       // a2: (o0,   c0+4)
    v.w = f2tf32(wpw[(size_t)(o0 + 8) * CIN + c0 + 4]); // a3: (o0+8, c0+4)
    wA_buf[t] = v;
}

__global__ __launch_bounds__(256, 2)
void fused_upconv_kernel(const float* __restrict__ x,
                         const float* __restrict__ wdw,
                         float* __restrict__ out)
{
    extern __shared__ float smem[];
    float*    s_in = smem;                   // [NY*NX][SPAD]      (phase 1)
    uint32_t* sdwB = (uint32_t*)smem;        // [64 px][BP2] words (phase 2, aliases)

    const int tileX = blockIdx.x;   // 0..9
    const int tileY = blockIdx.y;   // 0..29
    const int b     = blockIdx.z;   // 0..7
    const int tid   = threadIdx.x;

    const int r0  = tileY * TR;
    const int xo0 = tileX * TC;

    const int y_lo = (int)((float)r0 * CYc);
    const int ixb  = (int)((float)xo0 * CXc);

    // ---- Stage input patch: thread = (patch position, channel group).
    //      All index math hoisted; body is pure LDG+STS with const strides. ----
    {
        const int pos  = tid & 63;          // 0..63, 0..59 valid
        const int cgrp = tid >> 6;          // 0..3
        if (pos < NY * NX) {
            const int yy = pos / NX;
            const int ix = pos - yy * NX;
            const int gy = min(y_lo + yy, HIN - 1);
            const int gx = min(ixb + ix, WIN - 1);
            const float* gp = x + (size_t)b * CIN * (HIN * WIN)
                                + (size_t)cgrp * (HIN * WIN) + gy * WIN + gx;
            float* sp = s_in + pos * SPAD + cgrp;
            #pragma unroll 16
            for (int k = 0; k < 64; k++)
                sp[k * 4] = __ldg(gp + (size_t)k * 4 * (HIN * WIN));
        }
    }
    __syncthreads();

    // ---- Phase 1: bilinear + 3x3 depthwise, channel c = tid, all in regs ----
    float acc[TR][TC];
    {
        const int c = tid;
        float wd[9];
        #pragma unroll
        for (int i = 0; i < 9; i++) wd[i] = __ldg(&wdw[c * 9 + i]);

        #pragma unroll
        for (int r = 0; r < TR; r++)
            #pragma unroll
            for (int q = 0; q < TC; q++) acc[r][q] = 0.0f;

        #pragma unroll
        for (int rho = 0; rho < 6; rho++) {
            const int R = r0 + rho;
            float hy = (float)R * CYc;
            int   y0 = (int)hy;
            float fy = hy - (float)y0;
            int   y1 = min(y0 + 1, HIN - 1);
            float ofy = 1.0f - fy;
            const float* p0 = s_in + (y0 - y_lo) * (NX * SPAD) + c;
            const float* p1 = s_in + (y1 - y_lo) * (NX * SPAD) + c;

            float vt[12];
            #pragma unroll
            for (int i = 0; i < 12; i++)
                vt[i] = p0[i * SPAD] * ofy + p1[i * SPAD] * fy;

            float u[18];
            horiz_dispatch(tileX, vt, u);

            #pragma unroll
            for (int dy = 0; dy < 3; dy++) {
                int r = rho - dy;
                if (r < 0 || r >= TR) continue;   // compile-time folded
                #pragma unroll
                for (int dx = 0; dx < 3; dx++) {
                    float wv = wd[dy * 3 + dx];
                    #pragma unroll
                    for (int q = 0; q < TC; q++)
                        acc[r][q] += wv * u[q + dx];
                }
            }
        }
    }
    __syncthreads();   // s_in reads done -> safe to alias with sdwB

    // ---- Store dw tile, tf32: word = p*BP2 + (c>>3)*8 + inner.
    //      Lane->bank map is a bijection -> conflict-free stores. ----
    {
        const int c = tid;
        const int soff = ((c >> 3) << 3) | (((c & 3) << 1) | ((c >> 2) & 1));
        uint32_t* sp = sdwB + soff;
        #pragma unroll
        for (int p = 0; p < 64; p++)
            sp[p * BP2] = f2tf32(acc[p >> 4][p & 15]);
    }
    __syncthreads();

    // ---- Phase 2: tf32 mma GEMM, m32n32 per warp, LDS.64 B fragments ----
    {
        const int wid  = tid >> 5;
        const int lane = tid & 31;
        const int gid  = lane >> 2;
        const int tig  = lane & 3;
        const int mg   = wid >> 1;    // 0..3 -> out channels 32*mg..
        const int ng   = wid & 1;     // 0..1 -> pixels 32*ng..

        float d[2][4][4];
        #pragma unroll
        for (int mt = 0; mt < 2; mt++)
            #pragma unroll
            for (int nt = 0; nt < 4; nt++)
                #pragma unroll
                for (int i = 0; i < 4; i++) d[mt][nt][i] = 0.0f;

        const uint4* wAp0 = wA_buf + (size_t)(2 * mg) * 32 * 32 + lane;
        const uint4* wAp1 = wAp0 + 32 * 32;

        const uint32_t* bp[4];
        #pragma unroll
        for (int nt = 0; nt < 4; nt++)
            bp[nt] = sdwB + (ng * 32 + nt * 8 + gid) * BP2 + 2 * tig;

        #pragma unroll 8
        for (int ks = 0; ks < 32; ks++) {
            uint4 a0 = __ldg(wAp0 + ks * 32);
            uint4 a1 = __ldg(wAp1 + ks * 32);
            #pragma unroll
            for (int nt = 0; nt < 4; nt++) {
                uint2 bb = *(const uint2*)(bp[nt] + ks * 8);  // k=tig, k=tig+4
                mma_tf32(d[0][nt], a0, bb.x, bb.y);
                mma_tf32(d[1][nt], a1, bb.x, bb.y);
            }
        }

        // writeback: c0,c1 -> row (o), c2,c3 -> row (o+8)
        #pragma unroll
        for (int mt = 0; mt < 2; mt++) {
            int o = mg * 32 + mt * 16 + gid;
            #pragma unroll
            for (int nt = 0; nt < 4; nt++) {
                int p = ng * 32 + nt * 8 + 2 * tig;
                int h = r0 + (p >> 4);
                int w = xo0 + (p & 15);
                size_t base0 = (((size_t)b * COUT + o) * HOUT + h) * (size_t)WOUT + w;
                size_t base1 = (((size_t)b * COUT + o + 8) * HOUT + h) * (size_t)WOUT + w;
                *(float2*)&out[base0] = make_float2(d[mt][nt][0], d[mt][nt][1]);
                *(float2*)&out[base1] = make_float2(d[mt][nt][2], d[mt][nt][3]);
            }
        }
    }
}

extern "C" void kernel_launch(void* const* d_in, const int* in_sizes, int n_in,
                              void* d_out, int out_size)
{
    const float* x   = (const float*)d_in[0];   // [8,256,60,80]
    const float* wdw = (const float*)d_in[1];   // [256,1,3,3]
    const float* wpw = (const float*)d_in[2];   // [128,256]
    float*       out = (float*)d_out;           // [8,128,120,160]
    (void)in_sizes; (void)n_in; (void)out_size;

    cudaFuncSetAttribute(fused_upconv_kernel,
                         cudaFuncAttributeMaxDynamicSharedMemorySize, SMEM_BYTES);

    repack_w_kernel<<<32, 256>>>(wpw);

    dim3 grid(WOUT / TC, HOUT / TR, 8);   // (10, 30, 8)
    fused_upconv_kernel<<<grid, 256, SMEM_BYTES>>>(x, wdw, out);
}